// round 10
// baseline (speedup 1.0000x reference)
#include <cuda_runtime.h>

// PLE layers, round 10: HMMA tf32, 512-thread CTA, 16 warps/SM (regfile-fit).
//   tcgen05 unavailable (harness PTX target is sm_103 base) -> legacy mma.sync.
//   Register ceiling broken by folding out_a/out_b per-expert via gmem RMW
//   (CTA-exclusive rows, L2-resident); only out_s kept in registers.
//   TB=128 rows/CTA halves W L2 traffic; 3-slot cp.async ring, one barrier
//   per 32-K chunk; warp tile 32x32 on a 4x4 warp grid.

#define BT      16384
#define IN_D    256
#define EXP_D   128
#define NE      8
#define TB      128         // batch rows per CTA
#define KC      32          // K chunk
#define NBUF    3           // W smem ring depth
#define XSS     260         // x smem stride (words): bank = 4*gid+tig, conflict-free
#define WSS     136         // w smem stride (words): bank = 8*tig+gid, conflict-free
#define GSS     57          // gate-weight smem stride
#define NTH     512
#define WSTK    (NE*IN_D*EXP_D)   // floats per W stack = 262144
#define NCHUNK  192               // 3 stacks * 8 experts * 8 chunks

__device__ float Wc_scratch[3 * WSTK];   // RN-tf32-converted W banks (3.1 MB)

__device__ __forceinline__ unsigned f2tf(float f) {
    unsigned u;
    asm("cvt.rna.tf32.f32 %0, %1;" : "=r"(u) : "f"(f));
    return u;
}

__device__ __forceinline__ void cp16(float* smem_dst, const float* gsrc) {
    unsigned d = (unsigned)__cvta_generic_to_shared(smem_dst);
    asm volatile("cp.async.cg.shared.global [%0], [%1], 16;\n" :: "r"(d), "l"(gsrc));
}
__device__ __forceinline__ void cp_commit() { asm volatile("cp.async.commit_group;\n"); }
template<int N> __device__ __forceinline__ void cp_wait() {
    asm volatile("cp.async.wait_group %0;\n" :: "n"(N));
}

__device__ __forceinline__ void mma8(float& c0, float& c1, float& c2, float& c3,
                                     unsigned a0, unsigned a1, unsigned a2, unsigned a3,
                                     unsigned b0, unsigned b1) {
    asm volatile(
        "mma.sync.aligned.m16n8k8.row.col.f32.tf32.tf32.f32 "
        "{%0,%1,%2,%3}, {%4,%5,%6,%7}, {%8,%9}, {%0,%1,%2,%3};\n"
        : "+f"(c0), "+f"(c1), "+f"(c2), "+f"(c3)
        : "r"(a0), "r"(a1), "r"(a2), "r"(a3), "r"(b0), "r"(b1));
}

// ---------------- prepass: RN-convert W banks to tf32 bits ----------------
__global__ void w_convert_kernel(const float* __restrict__ Wa,
                                 const float* __restrict__ Wb,
                                 const float* __restrict__ Wsx) {
    int i4 = blockIdx.x * blockDim.x + threadIdx.x;     // one float4 per thread
    int s  = i4 / (WSTK / 4);
    int o4 = i4 - s * (WSTK / 4);
    const float* src = (s == 0) ? Wa : (s == 1) ? Wb : Wsx;
    float4 v = __ldg((const float4*)src + o4);
    uint4 u;
    u.x = f2tf(v.x); u.y = f2tf(v.y); u.z = f2tf(v.z); u.w = f2tf(v.w);
    *((uint4*)(Wc_scratch + (size_t)s * WSTK) + o4) = u;
}

// ---------------- main fused kernel ----------------
__global__ __launch_bounds__(NTH, 1)
void ple_kernel(const float* __restrict__ xa, const float* __restrict__ xb,
                const float* __restrict__ xsh,
                const float* __restrict__ ba, const float* __restrict__ bb,
                const float* __restrict__ bsx,
                const float* __restrict__ Ga, const float* __restrict__ Gb,
                const float* __restrict__ Gq,
                float* __restrict__ out)
{
    extern __shared__ float smem[];
    float* xs  = smem;                       // TB*XSS     : x tile (raw fp32 bits)
    float* ws  = xs + TB * XSS;              // NBUF*KC*WSS: W ring (tf32 bits)
    float* wsm = ws + NBUF * KC * WSS;       // TB*GSS     : gate weights
    float* bsm = wsm + TB * GSS;             // 3*1024     : biases

    const int tid  = threadIdx.x;
    const int lane = tid & 31;
    const int wid  = tid >> 5;
    const int gid  = lane >> 2;
    const int tig  = lane & 3;
    const int wm   = wid >> 2;               // 0..3 (row warp)
    const int wn   = wid & 3;                // 0..3 (col warp)
    const int row0 = blockIdx.x * TB;
    const size_t OS = (size_t)BT * EXP_D;

    for (int i = tid; i < 1024; i += NTH) {
        bsm[i]        = __ldg(ba + i);
        bsm[1024 + i] = __ldg(bb + i);
        bsm[2048 + i] = __ldg(bsx + i);
    }

    // X tile loader: 128 rows x 64 float4 = 8192 segments, 16 per thread (plain LDG/STS)
    auto stage_x = [&](const float* X) {
        const float4* src = (const float4*)(X + (size_t)row0 * IN_D);
        #pragma unroll
        for (int j = 0; j < 16; ++j) {
            int idx = tid + j * NTH;
            int r = idx >> 6, s4 = idx & 63;
            *(float4*)(xs + r * XSS + s4 * 4) = __ldg(src + idx);
        }
    };

    // ---------------- Phase 1: all gate logits + softmax (full fp32) ----------------
    #pragma unroll 1
    for (int sg = 0; sg < 3; ++sg) {
        const float* X = (sg == 0) ? xa : (sg == 1) ? xb : xsh;
        const float* G = (sg == 0) ? Ga : (sg == 1) ? Gb : Gq;
        const int NG   = (sg == 2) ? 24 : 16;
        const int WOFF = sg * 16;

        __syncthreads();
        stage_x(X);
        __syncthreads();

        for (int idx = tid; idx < TB * NG; idx += NTH) {
            int r = idx / NG, g = idx - r * NG;
            const float4* xp = (const float4*)(xs + r * XSS);
            const float4* gp = (const float4*)(G + (size_t)g * IN_D);
            float acc = 0.f;
            #pragma unroll 8
            for (int k = 0; k < IN_D / 4; ++k) {
                float4 xv = xp[k];
                float4 gv = __ldg(gp + k);
                acc += xv.x * gv.x; acc += xv.y * gv.y;
                acc += xv.z * gv.z; acc += xv.w * gv.w;
            }
            wsm[r * GSS + WOFF + g] = acc;
        }
        __syncthreads();

        if (tid < TB) {
            float* wr = wsm + tid * GSS + WOFF;
            float m = wr[0];
            for (int g = 1; g < NG; ++g) m = fmaxf(m, wr[g]);
            float s = 0.f;
            for (int g = 0; g < NG; ++g) { float e = expf(wr[g] - m); wr[g] = e; s += e; }
            float inv = 1.f / s;
            for (int g = 0; g < NG; ++g) wr[g] *= inv;
        }
    }
    __syncthreads();

    // ---------------- Phase 2: expert GEMMs, per-expert folds ----------------
    float osr[2][4][4] = {};     // out_s accumulators (kept in registers)
    float ec[2][4][4];

    // W chunk q (q = sg*64 + e*8 + c): 32 rows x 32 float4 = 1024 segs, 2 per thread
    auto issue_chunk = [&](int q) {
        const float* src = Wc_scratch + (size_t)(q >> 6) * WSTK
                           + (size_t)((q >> 3) & 7) * IN_D * EXP_D
                           + (q & 7) * KC * EXP_D;
        float* dst = ws + (q % NBUF) * (KC * WSS);
        #pragma unroll
        for (int j = 0; j < 2; ++j) {
            int idx = tid + j * NTH;
            int r = idx >> 5, s4 = (idx & 31) << 2;
            cp16(dst + r * WSS + s4, src + r * EXP_D + s4);
        }
        cp_commit();
    };

    issue_chunk(0);
    issue_chunk(1);

    #pragma unroll 1
    for (int q = 0; q < NCHUNK; ++q) {
        const int c  = q & 7;
        const int e  = (q >> 3) & 7;
        const int sg = q >> 6;

        if (q < NCHUNK - 1) cp_wait<1>(); else cp_wait<0>();
        __syncthreads();                       // chunk q landed; MMAs of q-1 done

        if ((q & 63) == 0) {                   // stack boundary: restage X
            stage_x((sg == 0) ? xa : (sg == 1) ? xb : xsh);
            __syncthreads();
        }

        if (q + 2 < NCHUNK) issue_chunk(q + 2);  // slot of q-1, now free

        if (c == 0) {
            #pragma unroll
            for (int mt = 0; mt < 2; ++mt)
                #pragma unroll
                for (int nt = 0; nt < 4; ++nt)
                    #pragma unroll
                    for (int v = 0; v < 4; ++v) ec[mt][nt][v] = 0.f;
        }

        const float* wb = ws + (q % NBUF) * (KC * WSS);

        #pragma unroll
        for (int kk = 0; kk < KC / 8; ++kk) {
            unsigned fa[8], fb[8];
            #pragma unroll
            for (int mt = 0; mt < 2; ++mt) {
                const float* xr = xs + (wm * 32 + mt * 16 + gid) * XSS + c * KC + kk * 8;
                fa[mt * 4 + 0] = __float_as_uint(xr[tig]);
                fa[mt * 4 + 1] = __float_as_uint(xr[8 * XSS + tig]);
                fa[mt * 4 + 2] = __float_as_uint(xr[tig + 4]);
                fa[mt * 4 + 3] = __float_as_uint(xr[8 * XSS + tig + 4]);
            }
            #pragma unroll
            for (int nt = 0; nt < 4; ++nt) {
                int n = wn * 32 + nt * 8 + gid;
                fb[nt * 2 + 0] = __float_as_uint(wb[(kk * 8 + tig) * WSS + n]);
                fb[nt * 2 + 1] = __float_as_uint(wb[(kk * 8 + tig + 4) * WSS + n]);
            }
            #pragma unroll
            for (int nt = 0; nt < 4; ++nt)
                #pragma unroll
                for (int mt = 0; mt < 2; ++mt)
                    mma8(ec[mt][nt][0], ec[mt][nt][1], ec[mt][nt][2], ec[mt][nt][3],
                         fa[mt * 4 + 0], fa[mt * 4 + 1], fa[mt * 4 + 2], fa[mt * 4 + 3],
                         fb[nt * 2 + 0], fb[nt * 2 + 1]);
        }

        if (c == 7) {
            // ---- fold expert e of stack sg ----
            #pragma unroll
            for (int mt = 0; mt < 2; ++mt) {
                int rl = wm * 32 + mt * 16 + gid;
                const float* wr0 = wsm + rl * GSS;
                const float* wr1 = wsm + (rl + 8) * GSS;
                float wA0 = 0.f, wA1 = 0.f, wB0 = 0.f, wB1 = 0.f, wS0, wS1;
                if (sg == 0) {
                    wA0 = wr0[e];      wA1 = wr1[e];
                    wS0 = wr0[32 + e]; wS1 = wr1[32 + e];
                } else if (sg == 1) {
                    wB0 = wr0[16 + e]; wB1 = wr1[16 + e];
                    wS0 = wr0[40 + e]; wS1 = wr1[40 + e];
                } else {
                    wA0 = wr0[8 + e];  wA1 = wr1[8 + e];
                    wB0 = wr0[24 + e]; wB1 = wr1[24 + e];
                    wS0 = wr0[48 + e]; wS1 = wr1[48 + e];
                }
                size_t r0off = (size_t)(row0 + rl) * EXP_D;
                size_t r1off = (size_t)(row0 + rl + 8) * EXP_D;
                #pragma unroll
                for (int nt = 0; nt < 4; ++nt) {
                    int c0 = wn * 32 + nt * 8 + 2 * tig;
                    const float* bp = bsm + sg * 1024 + e * EXP_D + c0;
                    float b0 = bp[0], b1 = bp[1];
                    float t0 = ec[mt][nt][0] + b0, t1 = ec[mt][nt][1] + b1;
                    float t2 = ec[mt][nt][2] + b0, t3 = ec[mt][nt][3] + b1;

                    osr[mt][nt][0] += wS0 * t0; osr[mt][nt][1] += wS0 * t1;
                    osr[mt][nt][2] += wS1 * t2; osr[mt][nt][3] += wS1 * t3;

                    if (sg != 1) {   // out_a RMW
                        float2* p0 = (float2*)(out + r0off + c0);
                        float2* p1 = (float2*)(out + r1off + c0);
                        if (sg == 0 && e == 0) {
                            *p0 = make_float2(wA0 * t0, wA0 * t1);
                            *p1 = make_float2(wA1 * t2, wA1 * t3);
                        } else {
                            float2 v0 = *p0, v1 = *p1;
                            v0.x += wA0 * t0; v0.y += wA0 * t1;
                            v1.x += wA1 * t2; v1.y += wA1 * t3;
                            *p0 = v0; *p1 = v1;
                        }
                    }
                    if (sg != 0) {   // out_b RMW
                        float2* p0 = (float2*)(out + OS + r0off + c0);
                        float2* p1 = (float2*)(out + OS + r1off + c0);
                        if (sg == 1 && e == 0) {
                            *p0 = make_float2(wB0 * t0, wB0 * t1);
                            *p1 = make_float2(wB1 * t2, wB1 * t3);
                        } else {
                            float2 v0 = *p0, v1 = *p1;
                            v0.x += wB0 * t0; v0.y += wB0 * t1;
                            v1.x += wB1 * t2; v1.y += wB1 * t3;
                            *p0 = v0; *p1 = v1;
                        }
                    }
                }
            }
        }
    }

    // ---------------- write out_s ----------------
    #pragma unroll
    for (int mt = 0; mt < 2; ++mt) {
        int r = row0 + wm * 32 + mt * 16 + gid;
        #pragma unroll
        for (int nt = 0; nt < 4; ++nt) {
            int c0 = wn * 32 + nt * 8 + 2 * tig;
            *(float2*)(out + 2 * OS + (size_t)r * EXP_D + c0) =
                make_float2(osr[mt][nt][0], osr[mt][nt][1]);
            *(float2*)(out + 2 * OS + (size_t)(r + 8) * EXP_D + c0) =
                make_float2(osr[mt][nt][2], osr[mt][nt][3]);
        }
    }
}

extern "C" void kernel_launch(void* const* d_in, const int* in_sizes, int n_in,
                              void* d_out, int out_size) {
    (void)in_sizes; (void)n_in; (void)out_size;

    w_convert_kernel<<<3 * WSTK / 4 / NTH, NTH>>>(
        (const float*)d_in[3], (const float*)d_in[5], (const float*)d_in[7]);

    constexpr int SMEM_BYTES =
        (TB * XSS + NBUF * KC * WSS + TB * GSS + 3 * 1024) * 4;   // 226,816 B
    cudaFuncSetAttribute(ple_kernel, cudaFuncAttributeMaxDynamicSharedMemorySize, SMEM_BYTES);
    ple_kernel<<<BT / TB, NTH, SMEM_BYTES>>>(
        (const float*)d_in[0], (const float*)d_in[1], (const float*)d_in[2],
        (const float*)d_in[4], (const float*)d_in[6], (const float*)d_in[8],
        (const float*)d_in[9], (const float*)d_in[10], (const float*)d_in[11],
        (float*)d_out);
}

// round 11
// speedup vs baseline: 1.2822x; 1.2822x over previous
#include <cuda_runtime.h>
#include <cuda_fp16.h>

// PLE layers, round 11: fp16 HMMA (m16n8k16, fp32 accum).
//   Model: legacy mma.sync on sm_103a is instruction-rate-limited (~10.7
//   cyc/HMMA/SM across R5/R7/R10). k16.f16 carries 2x MACs/instr vs k8.tf32
//   at identical 11-bit operand mantissa -> half the instructions, same
//   accuracy. Gates keep a raw-fp32 X path. Structure otherwise = R7 best:
//   TB=64 rows/CTA, 256 thr, 8 warps (2x4), warp tile 32x32, 4-slot
//   cp.async W ring, register-resident fused outputs.

#define BT      16384
#define IN_D    256
#define EXP_D   128
#define NE      8
#define TB      64
#define NTH     256
#define XSSF    260         // phase-1 fp32 X stride (words)
#define XS2     132         // phase-2 half2 X stride (uints): 132 % 32 = 4 -> conflict-free
#define WS2     136         // W chunk stride (uints): 136 % 32 = 8 -> conflict-free
#define GSS     57
#define NBUF    4
#define CH_U    2048        // uints per W chunk: 16 kp x 128 n (8 KB)
#define CH_ROWS 16          // k-pairs per chunk (= 32 k)

// smem word offsets (union: phase1 fp32 X vs phase2 fp16 X + W ring)
#define OFF_XS   0
#define OFF_WS   8448                       // 64*132
#define OFF_WSM  17152                      // max(16640, 8448+4*16*136)
#define OFF_BSM  (OFF_WSM + TB*GSS)         // +3648
#define SMEM_WORDS (OFF_BSM + 3*1024)       // 23872 words = 95488 B

__device__ unsigned Wc2[3 * NE * 128 * 128];   // fp16x2 W, [sg][e][kp][n] (1.57 MB)

__device__ __forceinline__ void cp16(void* smem_dst, const void* gsrc) {
    unsigned d = (unsigned)__cvta_generic_to_shared(smem_dst);
    asm volatile("cp.async.cg.shared.global [%0], [%1], 16;\n" :: "r"(d), "l"(gsrc));
}
__device__ __forceinline__ void cp_commit() { asm volatile("cp.async.commit_group;\n"); }
template<int N> __device__ __forceinline__ void cp_wait() {
    asm volatile("cp.async.wait_group %0;\n" :: "n"(N));
}

__device__ __forceinline__ void mma16(float& c0, float& c1, float& c2, float& c3,
                                      unsigned a0, unsigned a1, unsigned a2, unsigned a3,
                                      unsigned b0, unsigned b1) {
    asm volatile(
        "mma.sync.aligned.m16n8k16.row.col.f32.f16.f16.f32 "
        "{%0,%1,%2,%3}, {%4,%5,%6,%7}, {%8,%9}, {%0,%1,%2,%3};\n"
        : "+f"(c0), "+f"(c1), "+f"(c2), "+f"(c3)
        : "r"(a0), "r"(a1), "r"(a2), "r"(a3), "r"(b0), "r"(b1));
}

// ---------------- prepass: W[e][k][n] -> fp16x2 k-pairs, [sg][e][kp][n] ----------------
__global__ void w_convert2(const float* __restrict__ Wa, const float* __restrict__ Wb,
                           const float* __restrict__ Wsx) {
    int id = blockIdx.x * blockDim.x + threadIdx.x;   // 393216 threads
    int n  = id & 127;
    int kp = (id >> 7) & 127;
    int e  = (id >> 14) & 7;
    int sg = id >> 17;
    const float* W = (sg == 0) ? Wa : (sg == 1) ? Wb : Wsx;
    const float* p = W + ((size_t)e * IN_D + 2 * kp) * EXP_D + n;
    __half2 h = __floats2half2_rn(p[0], p[EXP_D]);    // low = even k
    Wc2[id] = *(unsigned*)&h;
}

// ---------------- main fused kernel ----------------
__global__ __launch_bounds__(NTH, 1)
void ple_kernel(const float* __restrict__ xa, const float* __restrict__ xb,
                const float* __restrict__ xsh,
                const float* __restrict__ ba, const float* __restrict__ bb,
                const float* __restrict__ bsx,
                const float* __restrict__ Ga, const float* __restrict__ Gb,
                const float* __restrict__ Gq,
                float* __restrict__ out)
{
    extern __shared__ float smem[];
    float*    xsf = smem + OFF_XS;            // phase 1: fp32 X tile
    unsigned* xs2 = (unsigned*)(smem + OFF_XS);   // phase 2: half2 X tile
    unsigned* wsu = (unsigned*)(smem + OFF_WS);   // phase 2: W ring
    float*    wsm = smem + OFF_WSM;           // gate weights
    float*    bsm = smem + OFF_BSM;           // biases

    const int tid  = threadIdx.x;
    const int lane = tid & 31;
    const int wid  = tid >> 5;
    const int gid  = lane >> 2;
    const int tig  = lane & 3;
    const int wm   = wid >> 2;                // 0..1
    const int wn   = wid & 3;                 // 0..3
    const int row0 = blockIdx.x * TB;

    for (int i = tid; i < 1024; i += NTH) {
        bsm[i]        = __ldg(ba + i);
        bsm[1024 + i] = __ldg(bb + i);
        bsm[2048 + i] = __ldg(bsx + i);
    }

    // ---------------- Phase 1: gate logits + softmax on RAW fp32 X ----------------
    #pragma unroll 1
    for (int sg = 0; sg < 3; ++sg) {
        const float* X = (sg == 0) ? xa : (sg == 1) ? xb : xsh;
        const float* G = (sg == 0) ? Ga : (sg == 1) ? Gb : Gq;
        const int NG   = (sg == 2) ? 24 : 16;
        const int WOFF = sg * 16;

        __syncthreads();
        {   // cp.async raw fp32 X tile: 64 rows x 64 float4
            const float4* src = (const float4*)(X + (size_t)row0 * IN_D);
            #pragma unroll
            for (int j = 0; j < 16; ++j) {
                int idx = tid + j * NTH;
                int r = idx >> 6, s4 = (idx & 63) << 2;
                cp16(xsf + r * XSSF + s4, src + idx);
            }
            cp_commit();
        }
        cp_wait<0>();
        __syncthreads();

        for (int idx = tid; idx < TB * NG; idx += NTH) {
            int r = idx / NG, g = idx - r * NG;
            const float4* xp = (const float4*)(xsf + r * XSSF);
            const float4* gp = (const float4*)(G + (size_t)g * IN_D);
            float acc = 0.f;
            #pragma unroll 8
            for (int k = 0; k < IN_D / 4; ++k) {
                float4 xv = xp[k];
                float4 gv = __ldg(gp + k);
                acc += xv.x * gv.x; acc += xv.y * gv.y;
                acc += xv.z * gv.z; acc += xv.w * gv.w;
            }
            wsm[r * GSS + WOFF + g] = acc;
        }
        __syncthreads();

        if (tid < TB) {
            float* wr = wsm + tid * GSS + WOFF;
            float m = wr[0];
            for (int g = 1; g < NG; ++g) m = fmaxf(m, wr[g]);
            float s = 0.f;
            for (int g = 0; g < NG; ++g) { float e = expf(wr[g] - m); wr[g] = e; s += e; }
            float inv = 1.f / s;
            for (int g = 0; g < NG; ++g) wr[g] *= inv;
        }
    }

    // ---------------- Phase 2: fp16 expert GEMMs + gated fold ----------------
    float oa[2][4][4] = {}, ob[2][4][4] = {}, os[2][4][4] = {};
    float ec[2][4][4];

    #pragma unroll 1
    for (int sg = 0; sg < 3; ++sg) {
        const float* X = (sg == 0) ? xa : (sg == 1) ? xb : xsh;
        const unsigned* Wg = Wc2 + (size_t)sg * (NE * 128 * 128);

        __syncthreads();      // prior xs/ws readers done
        {   // stage X as half2: 64 rows x 64 float4 -> 128 half2/row
            const float4* src = (const float4*)(X + (size_t)row0 * IN_D);
            #pragma unroll
            for (int j = 0; j < 16; ++j) {
                int idx = tid + j * NTH;
                int r = idx >> 6, k4 = idx & 63;
                float4 v = __ldg(src + idx);
                __half2 h0 = __floats2half2_rn(v.x, v.y);
                __half2 h1 = __floats2half2_rn(v.z, v.w);
                uint2 u = { *(unsigned*)&h0, *(unsigned*)&h1 };
                *(uint2*)(xs2 + r * XS2 + 2 * k4) = u;
            }
        }

        // W chunk q (= e*8+c): 16 kp-rows x 128 n, linear 8KB image
        auto issue_chunk = [&](int q) {
            const unsigned* src = Wg + (size_t)q * CH_U;
            unsigned* dst = wsu + (q & (NBUF - 1)) * (CH_ROWS * WS2);
            #pragma unroll
            for (int j = 0; j < 2; ++j) {
                int idx = tid + j * NTH;            // 512 x 16B segments
                int r = idx >> 5, s4 = (idx & 31) << 2;
                cp16(dst + r * WS2 + s4, src + idx * 4);
            }
            cp_commit();
        };

        issue_chunk(0);
        issue_chunk(1);

        #pragma unroll 1
        for (int q = 0; q < 64; ++q) {
            const int c = q & 7;
            if (q + 2 < 64) issue_chunk(q + 2);
            if (q < 62)       cp_wait<2>();
            else if (q == 62) cp_wait<1>();
            else              cp_wait<0>();
            __syncthreads();    // chunk q landed; MMAs of q-NBUF+? done; X staged (q=0)

            if (c == 0) {
                #pragma unroll
                for (int mt = 0; mt < 2; ++mt)
                    #pragma unroll
                    for (int nt = 0; nt < 4; ++nt)
                        #pragma unroll
                        for (int v = 0; v < 4; ++v) ec[mt][nt][v] = 0.f;
            }

            const unsigned* wb = wsu + (q & (NBUF - 1)) * (CH_ROWS * WS2);

            #pragma unroll
            for (int kk = 0; kk < 2; ++kk) {        // two k16 steps per 32-K chunk
                unsigned fa[8], fb[8];
                #pragma unroll
                for (int mt = 0; mt < 2; ++mt) {
                    const unsigned* xr = xs2 + (wm * 32 + mt * 16 + gid) * XS2
                                             + c * 16 + kk * 8;
                    fa[mt * 4 + 0] = xr[tig];
                    fa[mt * 4 + 1] = xr[8 * XS2 + tig];
                    fa[mt * 4 + 2] = xr[tig + 4];
                    fa[mt * 4 + 3] = xr[8 * XS2 + tig + 4];
                }
                #pragma unroll
                for (int nt = 0; nt < 4; ++nt) {
                    int n = wn * 32 + nt * 8 + gid;
                    fb[nt * 2 + 0] = wb[(kk * 8 + tig) * WS2 + n];
                    fb[nt * 2 + 1] = wb[(kk * 8 + tig + 4) * WS2 + n];
                }
                #pragma unroll
                for (int nt = 0; nt < 4; ++nt)
                    #pragma unroll
                    for (int mt = 0; mt < 2; ++mt)
                        mma16(ec[mt][nt][0], ec[mt][nt][1], ec[mt][nt][2], ec[mt][nt][3],
                              fa[mt * 4 + 0], fa[mt * 4 + 1], fa[mt * 4 + 2], fa[mt * 4 + 3],
                              fb[nt * 2 + 0], fb[nt * 2 + 1]);
            }

            if (c == 7) {
                const int e = q >> 3;
                #pragma unroll
                for (int mt = 0; mt < 2; ++mt) {
                    int rl = wm * 32 + mt * 16 + gid;
                    float w1l, w1h, w2l, w2h, w3l = 0.f, w3h = 0.f;
                    if (sg == 0) {
                        w1l = wsm[rl * GSS + e];      w1h = wsm[(rl + 8) * GSS + e];
                        w2l = wsm[rl * GSS + 32 + e]; w2h = wsm[(rl + 8) * GSS + 32 + e];
                    } else if (sg == 1) {
                        w1l = wsm[rl * GSS + 16 + e]; w1h = wsm[(rl + 8) * GSS + 16 + e];
                        w2l = wsm[rl * GSS + 40 + e]; w2h = wsm[(rl + 8) * GSS + 40 + e];
                    } else {
                        w1l = wsm[rl * GSS + 8 + e];  w1h = wsm[(rl + 8) * GSS + 8 + e];
                        w2l = wsm[rl * GSS + 24 + e]; w2h = wsm[(rl + 8) * GSS + 24 + e];
                        w3l = wsm[rl * GSS + 48 + e]; w3h = wsm[(rl + 8) * GSS + 48 + e];
                    }
                    #pragma unroll
                    for (int nt = 0; nt < 4; ++nt) {
                        int c0 = wn * 32 + nt * 8 + 2 * tig;
                        const float* bp = bsm + sg * 1024 + e * EXP_D + c0;
                        float t0 = ec[mt][nt][0] + bp[0];
                        float t1 = ec[mt][nt][1] + bp[1];
                        float t2 = ec[mt][nt][2] + bp[0];
                        float t3 = ec[mt][nt][3] + bp[1];
                        if (sg == 0) {
                            oa[mt][nt][0] += w1l * t0; oa[mt][nt][1] += w1l * t1;
                            oa[mt][nt][2] += w1h * t2; oa[mt][nt][3] += w1h * t3;
                            os[mt][nt][0] += w2l * t0; os[mt][nt][1] += w2l * t1;
                            os[mt][nt][2] += w2h * t2; os[mt][nt][3] += w2h * t3;
                        } else if (sg == 1) {
                            ob[mt][nt][0] += w1l * t0; ob[mt][nt][1] += w1l * t1;
                            ob[mt][nt][2] += w1h * t2; ob[mt][nt][3] += w1h * t3;
                            os[mt][nt][0] += w2l * t0; os[mt][nt][1] += w2l * t1;
                            os[mt][nt][2] += w2h * t2; os[mt][nt][3] += w2h * t3;
                        } else {
                            oa[mt][nt][0] += w1l * t0; oa[mt][nt][1] += w1l * t1;
                            oa[mt][nt][2] += w1h * t2; oa[mt][nt][3] += w1h * t3;
                            ob[mt][nt][0] += w2l * t0; ob[mt][nt][1] += w2l * t1;
                            ob[mt][nt][2] += w2h * t2; ob[mt][nt][3] += w2h * t3;
                            os[mt][nt][0] += w3l * t0; os[mt][nt][1] += w3l * t1;
                            os[mt][nt][2] += w3h * t2; os[mt][nt][3] += w3h * t3;
                        }
                    }
                }
            }
        }
    }

    // ---------------- write out: [out_a | out_b | out_s], each [B,128] ----------------
    const size_t OS = (size_t)BT * EXP_D;
    #pragma unroll
    for (int mt = 0; mt < 2; ++mt) {
        int r = row0 + wm * 32 + mt * 16 + gid;
        #pragma unroll
        for (int nt = 0; nt < 4; ++nt) {
            int c0 = wn * 32 + nt * 8 + 2 * tig;
            size_t p0 = (size_t)r * EXP_D + c0;
            size_t p1 = (size_t)(r + 8) * EXP_D + c0;
            *(float2*)(out + p0)          = make_float2(oa[mt][nt][0], oa[mt][nt][1]);
            *(float2*)(out + p1)          = make_float2(oa[mt][nt][2], oa[mt][nt][3]);
            *(float2*)(out + OS + p0)     = make_float2(ob[mt][nt][0], ob[mt][nt][1]);
            *(float2*)(out + OS + p1)     = make_float2(ob[mt][nt][2], ob[mt][nt][3]);
            *(float2*)(out + 2 * OS + p0) = make_float2(os[mt][nt][0], os[mt][nt][1]);
            *(float2*)(out + 2 * OS + p1) = make_float2(os[mt][nt][2], os[mt][nt][3]);
        }
    }
}

extern "C" void kernel_launch(void* const* d_in, const int* in_sizes, int n_in,
                              void* d_out, int out_size) {
    (void)in_sizes; (void)n_in; (void)out_size;

    // prepass: 3*8*128*128 = 393216 half2 packs
    w_convert2<<<1536, NTH>>>((const float*)d_in[3], (const float*)d_in[5],
                              (const float*)d_in[7]);

    constexpr int SMEM_BYTES = SMEM_WORDS * 4;   // 95,488 B
    cudaFuncSetAttribute(ple_kernel, cudaFuncAttributeMaxDynamicSharedMemorySize, SMEM_BYTES);
    ple_kernel<<<BT / TB, NTH, SMEM_BYTES>>>(
        (const float*)d_in[0], (const float*)d_in[1], (const float*)d_in[2],
        (const float*)d_in[4], (const float*)d_in[6], (const float*)d_in[8],
        (const float*)d_in[9], (const float*)d_in[10], (const float*)d_in[11],
        (float*)d_out);
}